// round 3
// baseline (speedup 1.0000x reference)
#include <cuda_runtime.h>
#include <cstdint>

#define SEQ      2048
#define BATCH    256
#define INDIM    128
#define H        256
#define NCLS     10
#define KTOT     384      // H + INDIM (unified k dimension)
#define RROWS    4        // batch rows per cluster
#define NTHREADS 256

typedef unsigned long long ull;

// SMEM layout (bytes):
//   Wcat  : 192 kpairs * 64 jpairs * 16B = 196608
//   buf   : 2 phases * 384 k * 4 rows * 8B (dup-packed) = 24576   @ 196608
//   part  : 4 kq * 4 rows * 64 jp * 8B = 8192                     @ 221184
//   bias  : 64 * 8B                                               @ 229376
#define SMEM_BYTES 229888

__device__ float g_hT[H * BATCH];   // final hidden state, transposed [j][b]

// ---------- packed f32x2 helpers ----------
__device__ __forceinline__ void ffma2(ull &d, ull a, ull b) {
    asm("fma.rn.f32x2 %0, %1, %2, %0;" : "+l"(d) : "l"(a), "l"(b));
}
__device__ __forceinline__ ull fadd2(ull a, ull b) {
    ull d; asm("add.rn.f32x2 %0, %1, %2;" : "=l"(d) : "l"(a), "l"(b)); return d;
}
__device__ __forceinline__ ull pack2(float lo, float hi) {
    ull d;
    unsigned l = __float_as_uint(lo), h = __float_as_uint(hi);
    asm("mov.b64 %0, {%1, %2};" : "=l"(d) : "r"(l), "r"(h));
    return d;
}
__device__ __forceinline__ ull dup2(float v) {
    ull d;
    unsigned u = __float_as_uint(v);
    asm("mov.b64 %0, {%1, %1};" : "=l"(d) : "r"(u));
    return d;
}
__device__ __forceinline__ void unpack2(ull a, float &lo, float &hi) {
    unsigned l, h;
    asm("mov.b64 {%0, %1}, %2;" : "=r"(l), "=r"(h) : "l"(a));
    lo = __uint_as_float(l); hi = __uint_as_float(h);
}

// Accurate tanh built on __expf (MUFU.EX2, ~1e-7 rel err). Never tanhf:
// under --use_fast_math it would lower to tanh.approx (5e-4 err/step,
// which random-walks past the 1e-3 test threshold over 2048 steps).
__device__ __forceinline__ float tanh_acc(float x) {
    float a = fabsf(x);
    float e = __expf(-2.0f * a);
    float r = (1.0f - e) / (1.0f + e);
    return copysignf(r, x);
}

// ============================================================================
// Main scan kernel: 64 clusters x 2 CTAs; each cluster owns 4 batch rows;
// each CTA owns 128 j-columns (jbase = rank*128) and the matching 192 KB
// weight slice. Per step: matvec (4 x 128 x 384) -> reduce -> tanh ->
// exchange new h with peer via DSMEM -> cluster barrier.
// ============================================================================
__global__ void __cluster_dims__(2, 1, 1) __launch_bounds__(NTHREADS, 1)
rnn_scan_kernel(const float* __restrict__ x,
                const float* __restrict__ W_ih,
                const float* __restrict__ W_hh,
                const float* __restrict__ b_ih,
                const float* __restrict__ b_hh)
{
    extern __shared__ ull smem[];
    ull* Wsm  = smem;                 // as ulonglong2: [kk][jp]
    ull* buf  = smem + 196608 / 8;    // [phase][k][row] dup-packed ull
    ull* part = smem + 221184 / 8;    // [kq][row][jp]
    ull* bias = smem + 229376 / 8;    // [jp] {b[j0], b[j1]}

    const int tid = threadIdx.x;
    unsigned rank;
    asm("mov.u32 %0, %%cluster_ctarank;" : "=r"(rank));
    const int row_base = (int)(blockIdx.x >> 1) * RROWS;
    const int jbase    = (int)rank * 128;

    // ---- stage weights: entry (kk, jp) -> {pack(W[j0][k0],W[j1][k0]), pack(W[j0][k1],W[j1][k1])}
    for (int idx = tid; idx < 192 * 64; idx += NTHREADS) {
        int kk = idx >> 6, jp = idx & 63;
        int k0 = 2 * kk;
        int j0 = jbase + 2 * jp;
        float a0, a1, c0, c1;
        if (k0 < H) {
            const float* p0 = W_hh + j0 * H + k0;
            a0 = p0[0]; c0 = p0[1];
            a1 = p0[H]; c1 = p0[H + 1];
        } else {
            const float* p0 = W_ih + j0 * INDIM + (k0 - H);
            a0 = p0[0];       c0 = p0[1];
            a1 = p0[INDIM];   c1 = p0[INDIM + 1];
        }
        Wsm[idx * 2]     = pack2(a0, a1);
        Wsm[idx * 2 + 1] = pack2(c0, c1);
    }
    if (tid < 64) {
        int j0 = jbase + 2 * tid;
        bias[tid] = pack2(b_ih[j0] + b_hh[j0], b_ih[j0 + 1] + b_hh[j0 + 1]);
    }
    // h0 = 0 in buf[0]
    for (int i = tid; i < H * RROWS; i += NTHREADS) buf[i] = 0;
    // x[0] into buf[0] x-region
    for (int i = tid; i < INDIM * RROWS; i += NTHREADS) {
        int row = i >> 7, f = i & 127;
        float v = x[(size_t)(row_base + row) * INDIM + f];
        buf[(H + f) * 4 + row] = dup2(v);
    }
    __syncthreads();

    const int jp = tid & 63;
    const int kq = tid >> 6;    // 4 k-slices of 96

    for (int s = 0; s < SEQ; s++) {
        const int cur = s & 1;
        const int nxt = cur ^ 1;

        // prefetch x[s+1] (consumed ~3000 cycles later -> DRAM latency hidden)
        float xp0 = 0.f, xp1 = 0.f;
        if (s + 1 < SEQ) {
            const float* xs = x + ((size_t)(s + 1) * BATCH + row_base) * INDIM;
            xp0 = xs[(tid >> 7) * INDIM + (tid & 127)];
            xp1 = xs[((tid + 256) >> 7) * INDIM + (tid & 127)];
        }

        // ---- phase A: acc[row] over this thread's 96-k slice, j-pair jp ----
        ull acc0 = 0, acc1 = 0, acc2 = 0, acc3 = 0;
        const ulonglong2* Wp = ((const ulonglong2*)Wsm) + kq * 48 * 64 + jp;
        const ulonglong2* hp = ((const ulonglong2*)(buf + cur * KTOT * RROWS)) + kq * 96 * 2;
        #pragma unroll 8
        for (int kk = 0; kk < 48; kk++) {
            ulonglong2 w  = Wp[kk * 64];        // {W(j0,j1)@k, W(j0,j1)@k+1}
            ulonglong2 hA = hp[kk * 4 + 0];     // k   rows 0,1 (dup-packed)
            ulonglong2 hB = hp[kk * 4 + 1];     // k   rows 2,3
            ulonglong2 hC = hp[kk * 4 + 2];     // k+1 rows 0,1
            ulonglong2 hD = hp[kk * 4 + 3];     // k+1 rows 2,3
            ffma2(acc0, w.x, hA.x); ffma2(acc1, w.x, hA.y);
            ffma2(acc2, w.x, hB.x); ffma2(acc3, w.x, hB.y);
            ffma2(acc0, w.y, hC.x); ffma2(acc1, w.y, hC.y);
            ffma2(acc2, w.y, hD.x); ffma2(acc3, w.y, hD.y);
        }
        part[(kq * 4 + 0) * 64 + jp] = acc0;
        part[(kq * 4 + 1) * 64 + jp] = acc1;
        part[(kq * 4 + 2) * 64 + jp] = acc2;
        part[(kq * 4 + 3) * 64 + jp] = acc3;
        __syncthreads();

        // ---- reduce 4 k-slices, bias, tanh, write h[next] local + peer ----
        {
            const int pp  = tid & 63;
            const int row = tid >> 6;
            ull v = fadd2(fadd2(part[(0 + row) * 64 + pp],  part[(4 + row) * 64 + pp]),
                          fadd2(part[(8 + row) * 64 + pp],  part[(12 + row) * 64 + pp]));
            v = fadd2(v, bias[pp]);
            float lo, hi; unpack2(v, lo, hi);
            float t0 = tanh_acc(lo), t1 = tanh_acc(hi);
            int jg = jbase + 2 * pp;
            if (s == SEQ - 1) {
                g_hT[(size_t)jg * BATCH + row_base + row]       = t0;
                g_hT[(size_t)(jg + 1) * BATCH + row_base + row] = t1;
            } else {
                ull d0 = dup2(t0), d1 = dup2(t1);
                int e0 = (nxt * KTOT + jg) * 4 + row;   // k index = jg
                buf[e0]     = d0;
                buf[e0 + 4] = d1;
                unsigned la = (unsigned)__cvta_generic_to_shared(&buf[e0]);
                unsigned pa;
                asm("mapa.shared::cluster.u32 %0, %1, %2;" : "=r"(pa) : "r"(la), "r"(rank ^ 1u));
                asm volatile("st.shared::cluster.u64 [%0],    %1;" :: "r"(pa), "l"(d0));
                asm volatile("st.shared::cluster.u64 [%0+32], %1;" :: "r"(pa), "l"(d1));
            }
        }

        if (s + 1 < SEQ) {
            // stash prefetched x into buf[nxt]
            int f = tid & 127;
            buf[(nxt * KTOT + H + f) * 4 + (tid >> 7)]         = dup2(xp0);
            buf[(nxt * KTOT + H + f) * 4 + ((tid + 256) >> 7)] = dup2(xp1);
            // cluster barrier: release my DSMEM writes / acquire peer's;
            // also acts as the intra-CTA barrier for buf[nxt] and part reuse.
            asm volatile("barrier.cluster.arrive.aligned;" ::: "memory");
            asm volatile("barrier.cluster.wait.aligned;"   ::: "memory");
        }
    }
}

// ============================================================================
// Head: logits = h_last @ W_fc^T + b_fc, softmax over the BATCH axis (axis=1
// of (1,B,C) -- faithful to the reference). One CTA of 256 threads.
// ============================================================================
__global__ void __launch_bounds__(256)
head_kernel(const float* __restrict__ W_fc, const float* __restrict__ b_fc,
            float* __restrict__ out)
{
    __shared__ float Wsm[NCLS * H];
    __shared__ float logit[NCLS][BATCH];
    __shared__ float mred[NCLS], sred[NCLS];
    const int tid = threadIdx.x;   // = batch index b

    for (int i = tid; i < NCLS * H; i += 256) Wsm[i] = W_fc[i];
    __syncthreads();

    float acc[NCLS];
    #pragma unroll
    for (int c = 0; c < NCLS; c++) acc[c] = b_fc[c];
    for (int k = 0; k < H; k++) {
        float hv = g_hT[(size_t)k * BATCH + tid];   // coalesced
        #pragma unroll
        for (int c = 0; c < NCLS; c++) acc[c] += hv * Wsm[c * H + k];
    }
    #pragma unroll
    for (int c = 0; c < NCLS; c++) logit[c][tid] = acc[c];
    __syncthreads();

    if (tid < NCLS) {
        float m = -1e30f;
        for (int b = 0; b < BATCH; b++) m = fmaxf(m, logit[tid][b]);
        float ss = 0.f;
        for (int b = 0; b < BATCH; b++) ss += __expf(logit[tid][b] - m);
        mred[tid] = m;
        sred[tid] = 1.0f / ss;
    }
    __syncthreads();

    #pragma unroll
    for (int c = 0; c < NCLS; c++)
        out[tid * NCLS + c] = __expf(logit[c][tid] - mred[c]) * sred[c];
}

// ============================================================================
extern "C" void kernel_launch(void* const* d_in, const int* in_sizes, int n_in,
                              void* d_out, int out_size) {
    (void)in_sizes; (void)n_in; (void)out_size;
    const float* x    = (const float*)d_in[0];
    const float* W_ih = (const float*)d_in[1];
    const float* W_hh = (const float*)d_in[2];
    const float* b_ih = (const float*)d_in[3];
    const float* b_hh = (const float*)d_in[4];
    const float* W_fc = (const float*)d_in[5];
    const float* b_fc = (const float*)d_in[6];
    float* out = (float*)d_out;

    cudaFuncSetAttribute(rnn_scan_kernel,
                         cudaFuncAttributeMaxDynamicSharedMemorySize, SMEM_BYTES);

    rnn_scan_kernel<<<128, NTHREADS, SMEM_BYTES>>>(x, W_ih, W_hh, b_ih, b_hh);
    head_kernel<<<1, 256>>>(W_fc, b_fc, out);
}

// round 4
// speedup vs baseline: 1.1611x; 1.1611x over previous
#include <cuda_runtime.h>
#include <cstdint>

#define SEQ      2048
#define BATCH    256
#define INDIM    128
#define H        256
#define NCLS     10
#define KTOT     384      // H + INDIM (unified k dimension)
#define RROWS    4        // batch rows per cluster
#define NTHREADS 256

typedef unsigned long long ull;

// SMEM layout (bytes):
//   Wcat : 192 kpairs * 64 jpairs * 16B = 196608                  @ 0
//   buf  : 2 phases * 384 k * 4 rows * 8B (dup-packed) = 24576    @ 196608
//   part : 4 ks2 * 4 rows * 64 jp * 8B = 8192                     @ 221184
//   bias : 64 * 8B                                                @ 229376
#define SMEM_BYTES 229888

__device__ float g_hT[H * BATCH];   // final hidden state, transposed [j][b]

// ---------- packed f32x2 helpers ----------
__device__ __forceinline__ void ffma2(ull &d, ull a, ull b) {
    asm("fma.rn.f32x2 %0, %1, %2, %0;" : "+l"(d) : "l"(a), "l"(b));
}
__device__ __forceinline__ ull fadd2(ull a, ull b) {
    ull d; asm("add.rn.f32x2 %0, %1, %2;" : "=l"(d) : "l"(a), "l"(b)); return d;
}
__device__ __forceinline__ ull pack2(float lo, float hi) {
    ull d;
    unsigned l = __float_as_uint(lo), h = __float_as_uint(hi);
    asm("mov.b64 %0, {%1, %2};" : "=l"(d) : "r"(l), "r"(h));
    return d;
}
__device__ __forceinline__ ull dup2(float v) {
    ull d;
    unsigned u = __float_as_uint(v);
    asm("mov.b64 %0, {%1, %1};" : "=l"(d) : "r"(u));
    return d;
}
__device__ __forceinline__ void unpack2(ull a, float &lo, float &hi) {
    unsigned l, h;
    asm("mov.b64 {%0, %1}, %2;" : "=r"(l), "=r"(h) : "l"(a));
    lo = __uint_as_float(l); hi = __uint_as_float(h);
}

// Accurate tanh built on __expf (MUFU.EX2, ~1e-7 rel err). Never tanhf:
// tanh.approx error (5e-4/step) would random-walk past 1e-3 over 2048 steps.
__device__ __forceinline__ float tanh_acc(float x) {
    float a = fabsf(x);
    float e = __expf(-2.0f * a);
    float r = (1.0f - e) / (1.0f + e);
    return copysignf(r, x);
}

// ncu launch-parity shim: with order {dummy, scan, head, dummy} per call,
// ncu's "-s 5 -c 1" (skip 5, capture 6th) lands on the SCAN kernel.
__global__ void dummy_kernel() {}

// ============================================================================
// Main scan kernel: 64 clusters x 2 CTAs; each cluster owns 4 batch rows;
// each CTA owns 128 j-columns (jbase = rank*128). Config B: thread =
// (jq in 0..31, ks in 0..7); owns j-pairs {jq, jq+32} over k in
// [ks*48, ks*48+48). Each h broadcast feeds 16 ffma2 (was 8) -> shared
// crossbar wavefronts/step drop 3072 -> 2304.
// ============================================================================
__global__ void __cluster_dims__(2, 1, 1) __launch_bounds__(NTHREADS, 1)
rnn_scan_kernel(const float* __restrict__ x,
                const float* __restrict__ W_ih,
                const float* __restrict__ W_hh,
                const float* __restrict__ b_ih,
                const float* __restrict__ b_hh)
{
    extern __shared__ ull smem[];
    ull* Wsm  = smem;                 // as ulonglong2: [kk][jp]
    ull* buf  = smem + 196608 / 8;    // [phase][k][row] dup-packed ull
    ull* part = smem + 221184 / 8;    // [ks2][row][jp]
    ull* bias = smem + 229376 / 8;    // [jp] {b[j0], b[j1]}

    const int tid = threadIdx.x;
    unsigned rank;
    asm("mov.u32 %0, %%cluster_ctarank;" : "=r"(rank));
    const int row_base = (int)(blockIdx.x >> 1) * RROWS;
    const int jbase    = (int)rank * 128;

    // ---- stage weights: entry (kk, jp) -> {pack(W[j0][k0],W[j1][k0]), pack(W[j0][k1],W[j1][k1])}
    for (int idx = tid; idx < 192 * 64; idx += NTHREADS) {
        int kk = idx >> 6, jp = idx & 63;
        int k0 = 2 * kk;
        int j0 = jbase + 2 * jp;
        float a0, a1, c0, c1;
        if (k0 < H) {
            const float* p0 = W_hh + j0 * H + k0;
            a0 = p0[0]; c0 = p0[1];
            a1 = p0[H]; c1 = p0[H + 1];
        } else {
            const float* p0 = W_ih + j0 * INDIM + (k0 - H);
            a0 = p0[0];       c0 = p0[1];
            a1 = p0[INDIM];   c1 = p0[INDIM + 1];
        }
        Wsm[idx * 2]     = pack2(a0, a1);
        Wsm[idx * 2 + 1] = pack2(c0, c1);
    }
    if (tid < 64) {
        int j0 = jbase + 2 * tid;
        bias[tid] = pack2(b_ih[j0] + b_hh[j0], b_ih[j0 + 1] + b_hh[j0 + 1]);
    }
    // h0 = 0 in buf[0]
    for (int i = tid; i < H * RROWS; i += NTHREADS) buf[i] = 0;
    // x[0] into buf[0] x-region
    for (int i = tid; i < INDIM * RROWS; i += NTHREADS) {
        int row = i >> 7, f = i & 127;
        float v = x[(size_t)(row_base + row) * INDIM + f];
        buf[(H + f) * 4 + row] = dup2(v);
    }
    __syncthreads();

    const int jq = tid & 31;     // j-pair set: jp = jq and jq+32
    const int ks = tid >> 5;     // 8 k-slices of 48 k (24 kk) each

    for (int s = 0; s < SEQ; s++) {
        const int cur = s & 1;
        const int nxt = cur ^ 1;

        // prefetch x[s+1] (consumed ~3000 cycles later -> DRAM latency hidden)
        float xp0 = 0.f, xp1 = 0.f;
        if (s + 1 < SEQ) {
            const float* xs = x + ((size_t)(s + 1) * BATCH + row_base) * INDIM;
            xp0 = xs[(tid >> 7) * INDIM + (tid & 127)];
            xp1 = xs[((tid + 256) >> 7) * INDIM + (tid & 127)];
        }

        // ---- phase A: 2 j-pairs x 4 rows over this thread's 48-k slice ----
        ull a0 = 0, a1 = 0, a2 = 0, a3 = 0;   // j-pair jq,    rows 0..3
        ull b0 = 0, b1 = 0, b2 = 0, b3 = 0;   // j-pair jq+32, rows 0..3
        const ulonglong2* Wp = ((const ulonglong2*)Wsm) + ks * 24 * 64;
        const ulonglong2* hp = ((const ulonglong2*)(buf + cur * KTOT * RROWS)) + ks * 96;
        #pragma unroll 8
        for (int kk = 0; kk < 24; kk++) {
            ulonglong2 wa = Wp[kk * 64 + jq];
            ulonglong2 wb = Wp[kk * 64 + jq + 32];
            ulonglong2 hA = hp[kk * 4 + 0];     // k   rows 0,1 (dup-packed)
            ulonglong2 hB = hp[kk * 4 + 1];     // k   rows 2,3
            ulonglong2 hC = hp[kk * 4 + 2];     // k+1 rows 0,1
            ulonglong2 hD = hp[kk * 4 + 3];     // k+1 rows 2,3
            ffma2(a0, wa.x, hA.x); ffma2(a1, wa.x, hA.y);
            ffma2(a2, wa.x, hB.x); ffma2(a3, wa.x, hB.y);
            ffma2(b0, wb.x, hA.x); ffma2(b1, wb.x, hA.y);
            ffma2(b2, wb.x, hB.x); ffma2(b3, wb.x, hB.y);
            ffma2(a0, wa.y, hC.x); ffma2(a1, wa.y, hC.y);
            ffma2(a2, wa.y, hD.x); ffma2(a3, wa.y, hD.y);
            ffma2(b0, wb.y, hC.x); ffma2(b1, wb.y, hC.y);
            ffma2(b2, wb.y, hD.x); ffma2(b3, wb.y, hD.y);
        }

        // ---- two-stage k reduction in 8 KB part buffer ----
        if (ks < 4) {
            part[(ks * 4 + 0) * 64 + jq]      = a0;
            part[(ks * 4 + 1) * 64 + jq]      = a1;
            part[(ks * 4 + 2) * 64 + jq]      = a2;
            part[(ks * 4 + 3) * 64 + jq]      = a3;
            part[(ks * 4 + 0) * 64 + jq + 32] = b0;
            part[(ks * 4 + 1) * 64 + jq + 32] = b1;
            part[(ks * 4 + 2) * 64 + jq + 32] = b2;
            part[(ks * 4 + 3) * 64 + jq + 32] = b3;
        }
        __syncthreads();
        if (ks >= 4) {
            const int k2 = ks - 4;
            int i0 = (k2 * 4 + 0) * 64 + jq;
            int i1 = (k2 * 4 + 1) * 64 + jq;
            int i2 = (k2 * 4 + 2) * 64 + jq;
            int i3 = (k2 * 4 + 3) * 64 + jq;
            part[i0]      = fadd2(part[i0],      a0);
            part[i1]      = fadd2(part[i1],      a1);
            part[i2]      = fadd2(part[i2],      a2);
            part[i3]      = fadd2(part[i3],      a3);
            part[i0 + 32] = fadd2(part[i0 + 32], b0);
            part[i1 + 32] = fadd2(part[i1 + 32], b1);
            part[i2 + 32] = fadd2(part[i2 + 32], b2);
            part[i3 + 32] = fadd2(part[i3 + 32], b3);
        }
        __syncthreads();

        // ---- final reduce, bias, tanh, write h[next] local + peer ----
        {
            const int pp  = tid & 63;
            const int row = tid >> 6;
            ull v = fadd2(fadd2(part[(0 + row) * 64 + pp],  part[(4 + row) * 64 + pp]),
                          fadd2(part[(8 + row) * 64 + pp],  part[(12 + row) * 64 + pp]));
            v = fadd2(v, bias[pp]);
            float lo, hi; unpack2(v, lo, hi);
            float t0 = tanh_acc(lo), t1 = tanh_acc(hi);
            int jg = jbase + 2 * pp;
            if (s == SEQ - 1) {
                g_hT[(size_t)jg * BATCH + row_base + row]       = t0;
                g_hT[(size_t)(jg + 1) * BATCH + row_base + row] = t1;
            } else {
                ull d0 = dup2(t0), d1 = dup2(t1);
                int e0 = (nxt * KTOT + jg) * 4 + row;   // k index = jg
                buf[e0]     = d0;
                buf[e0 + 4] = d1;
                unsigned la = (unsigned)__cvta_generic_to_shared(&buf[e0]);
                unsigned pa;
                asm("mapa.shared::cluster.u32 %0, %1, %2;" : "=r"(pa) : "r"(la), "r"(rank ^ 1u));
                asm volatile("st.shared::cluster.u64 [%0],    %1;" :: "r"(pa), "l"(d0));
                asm volatile("st.shared::cluster.u64 [%0+32], %1;" :: "r"(pa), "l"(d1));
            }
        }

        if (s + 1 < SEQ) {
            // stash prefetched x into buf[nxt]
            int f = tid & 127;
            buf[(nxt * KTOT + H + f) * 4 + (tid >> 7)]         = dup2(xp0);
            buf[(nxt * KTOT + H + f) * 4 + ((tid + 256) >> 7)] = dup2(xp1);
            // cluster barrier: release my DSMEM writes / acquire peer's;
            // also the intra-CTA barrier for buf[nxt] and part reuse.
            asm volatile("barrier.cluster.arrive.aligned;" ::: "memory");
            asm volatile("barrier.cluster.wait.aligned;"   ::: "memory");
        }
    }
}

// ============================================================================
// Head: logits = h_last @ W_fc^T + b_fc, softmax over the BATCH axis (axis=1
// of (1,B,C) -- faithful to the reference). One CTA of 256 threads.
// k-loop unrolled x8 for MLP (was a serialized LDG chain: ~334 cyc/iter).
// ============================================================================
__global__ void __launch_bounds__(256)
head_kernel(const float* __restrict__ W_fc, const float* __restrict__ b_fc,
            float* __restrict__ out)
{
    __shared__ float Wsm[NCLS * H];
    __shared__ float logit[NCLS][BATCH];
    __shared__ float mred[NCLS], sred[NCLS];
    const int tid = threadIdx.x;   // = batch index b

    for (int i = tid; i < NCLS * H; i += 256) Wsm[i] = W_fc[i];
    __syncthreads();

    float acc[NCLS];
    #pragma unroll
    for (int c = 0; c < NCLS; c++) acc[c] = b_fc[c];
    #pragma unroll 1
    for (int k = 0; k < H; k += 8) {
        float hv[8];
        #pragma unroll
        for (int u = 0; u < 8; u++)
            hv[u] = g_hT[(size_t)(k + u) * BATCH + tid];   // 8 loads in flight
        #pragma unroll
        for (int u = 0; u < 8; u++) {
            #pragma unroll
            for (int c = 0; c < NCLS; c++)
                acc[c] += hv[u] * Wsm[c * H + k + u];
        }
    }
    #pragma unroll
    for (int c = 0; c < NCLS; c++) logit[c][tid] = acc[c];
    __syncthreads();

    if (tid < NCLS) {
        float m = -1e30f;
        for (int b = 0; b < BATCH; b++) m = fmaxf(m, logit[tid][b]);
        float ss = 0.f;
        for (int b = 0; b < BATCH; b++) ss += __expf(logit[tid][b] - m);
        mred[tid] = m;
        sred[tid] = 1.0f / ss;
    }
    __syncthreads();

    #pragma unroll
    for (int c = 0; c < NCLS; c++)
        out[tid * NCLS + c] = __expf(logit[c][tid] - mred[c]) * sred[c];
}

// ============================================================================
extern "C" void kernel_launch(void* const* d_in, const int* in_sizes, int n_in,
                              void* d_out, int out_size) {
    (void)in_sizes; (void)n_in; (void)out_size;
    const float* x    = (const float*)d_in[0];
    const float* W_ih = (const float*)d_in[1];
    const float* W_hh = (const float*)d_in[2];
    const float* b_ih = (const float*)d_in[3];
    const float* b_hh = (const float*)d_in[4];
    const float* W_fc = (const float*)d_in[5];
    const float* b_fc = (const float*)d_in[6];
    float* out = (float*)d_out;

    cudaFuncSetAttribute(rnn_scan_kernel,
                         cudaFuncAttributeMaxDynamicSharedMemorySize, SMEM_BYTES);

    // Launch order {dummy, scan, head, dummy}: ncu "-s 5 -c 1" then captures
    // the SCAN kernel (launch #6 = replay-1 scan), not head.
    dummy_kernel<<<1, 32>>>();
    rnn_scan_kernel<<<128, NTHREADS, SMEM_BYTES>>>(x, W_ih, W_hh, b_ih, b_hh);
    head_kernel<<<1, 256>>>(W_fc, b_fc, out);
    dummy_kernel<<<1, 32>>>();
}